// round 4
// baseline (speedup 1.0000x reference)
#include <cuda_runtime.h>
#include <cuda_bf16.h>
#include <cstdint>

// ---------------------------------------------------------------------------
// RingAttention: X -> Q,K,V proj (mma.sync 3xbf16) -> ring attention (fp32 SIMT)
//                -> O proj (mma.sync 3xbf16)
// B=1, S=4096, HIDDEN=1024, H=16, D=64, BLOCK=1024 (4 kv blocks)
// NOTE: toolchain targets compute_103 (no 'a' feature) -> tcgen05 unavailable;
//       use mma.sync (HMMA) + cp.async + ldmatrix, all baseline sm_80+.
// ---------------------------------------------------------------------------

#define S_LEN   4096
#define HID     1024
#define HEADS   16
#define HDIM    64
#define NBLK    4
#define KVBLK   1024

// fp32 scratch
__device__ float g_Q[HEADS * S_LEN * HDIM];
__device__ float g_K[HEADS * S_LEN * HDIM];
__device__ float g_V[HEADS * S_LEN * HDIM];
__device__ float g_A[S_LEN * HID];

// bf16 hi/lo split scratch
__device__ __nv_bfloat16 g_Xhi[S_LEN * HID];
__device__ __nv_bfloat16 g_Xlo[S_LEN * HID];
__device__ __nv_bfloat16 g_Ahi[S_LEN * HID];
__device__ __nv_bfloat16 g_Alo[S_LEN * HID];
__device__ __nv_bfloat16 g_Wh[4][HID * HID];   // transposed [n][k]
__device__ __nv_bfloat16 g_Wl[4][HID * HID];

// ---------------------------------------------------------------------------
// PTX helpers (baseline ISA only)
// ---------------------------------------------------------------------------
__device__ __forceinline__ uint32_t smem_u32(const void* p) {
    uint32_t a;
    asm("{ .reg .u64 t; cvta.to.shared.u64 t, %1; cvt.u32.u64 %0, t; }" : "=r"(a) : "l"(p));
    return a;
}

#define CP_ASYNC16(dst, src) \
    asm volatile("cp.async.cg.shared.global [%0], [%1], 16;" :: "r"(dst), "l"(src))
#define CP_COMMIT() asm volatile("cp.async.commit_group;" ::: "memory")
#define CP_WAIT0()  asm volatile("cp.async.wait_group 0;" ::: "memory")
#define CP_WAIT1()  asm volatile("cp.async.wait_group 1;" ::: "memory")

#define LDSM_X4(r0, r1, r2, r3, addr) \
    asm volatile("ldmatrix.sync.aligned.m8n8.x4.shared.b16 {%0,%1,%2,%3}, [%4];" \
                 : "=r"(r0), "=r"(r1), "=r"(r2), "=r"(r3) : "r"(addr))

#define MMA16816(d, a, b) \
    asm volatile("mma.sync.aligned.m16n8k16.row.col.f32.bf16.bf16.f32 " \
                 "{%0,%1,%2,%3}, {%4,%5,%6,%7}, {%8,%9}, {%0,%1,%2,%3};" \
                 : "+f"((d)[0]), "+f"((d)[1]), "+f"((d)[2]), "+f"((d)[3]) \
                 : "r"((a)[0]), "r"((a)[1]), "r"((a)[2]), "r"((a)[3]), \
                   "r"((b)[0]), "r"((b)[1]))

// ---------------------------------------------------------------------------
// hi/lo bf16 split conversion
// ---------------------------------------------------------------------------
__global__ __launch_bounds__(256) void convhl_k(const float* __restrict__ X,
                                                __nv_bfloat16* __restrict__ H,
                                                __nv_bfloat16* __restrict__ L)
{
    int i = (blockIdx.x * 256 + threadIdx.x) * 4;
    float4 v = *reinterpret_cast<const float4*>(X + i);
    __nv_bfloat16 h[4], l[4];
    float f[4] = {v.x, v.y, v.z, v.w};
#pragma unroll
    for (int j = 0; j < 4; j++) {
        h[j] = __float2bfloat16(f[j]);
        l[j] = __float2bfloat16(f[j] - __bfloat162float(h[j]));
    }
    *reinterpret_cast<uint2*>(H + i) = *reinterpret_cast<uint2*>(h);
    *reinterpret_cast<uint2*>(L + i) = *reinterpret_cast<uint2*>(l);
}

// transpose + hi/lo split: W[K][N] f32 -> Ht/Lt[N][K] bf16
__global__ __launch_bounds__(256) void convwt_k(const float* __restrict__ W,
                                                __nv_bfloat16* __restrict__ Ht,
                                                __nv_bfloat16* __restrict__ Lt)
{
    __shared__ float t[32][33];
    int n0 = blockIdx.x * 32, k0 = blockIdx.y * 32;
    int tx = threadIdx.x & 31, ty = threadIdx.x >> 5;
#pragma unroll
    for (int s = 0; s < 32; s += 8)
        t[ty + s][tx] = W[(size_t)(k0 + ty + s) * HID + n0 + tx];
    __syncthreads();
#pragma unroll
    for (int s = 0; s < 32; s += 8) {
        float v = t[tx][ty + s];
        __nv_bfloat16 h = __float2bfloat16(v);
        __nv_bfloat16 l = __float2bfloat16(v - __bfloat162float(h));
        size_t o = (size_t)(n0 + ty + s) * HID + k0 + tx;
        Ht[o] = h;
        Lt[o] = l;
    }
}

// ---------------------------------------------------------------------------
// HMMA 3xbf16 GEMM: C[4096,1024] = A @ Bt^T
//   A: Ah+Al bf16 row-major [m][k];  B: Bh+Bl bf16 row-major [n][k]
//   C = Ah*Bh + Ah*Bl + Al*Bh  (fp32 accum)
// CTA: 128x128 tile, 256 thr (8 warps, each 64x32), K-chunk 32, cp.async
// double buffer. SMEM rows pitch 80B (conflict-free ldmatrix).
// ---------------------------------------------------------------------------
#define GKC   32                       // K per chunk
#define GNC   (HID / GKC)              // 32 chunks
#define ARRB  (128 * 80)               // bytes per operand tile (pitch 80B)
#define BUFB  (4 * ARRB)               // 40960 B per buffer
#define EPIP  132                      // epilogue fp32 pitch

__global__ __launch_bounds__(256) void gemmmma_k(const __nv_bfloat16* __restrict__ Ah,
                                                 const __nv_bfloat16* __restrict__ Al,
                                                 const __nv_bfloat16* __restrict__ Bh,
                                                 const __nv_bfloat16* __restrict__ Bl,
                                                 float* __restrict__ C,
                                                 int headmajor)
{
    extern __shared__ char dsm[];
    const uint32_t sbase = smem_u32(dsm);

    const int tid  = threadIdx.x;
    const int wid  = tid >> 5;
    const int lane = tid & 31;
    const int m0 = blockIdx.y * 128;
    const int n0 = blockIdx.x * 128;
    const int m0w = (wid & 1) * 64;    // warp tile origin in CTA
    const int n0w = (wid >> 1) * 32;

    float acc[4][4][4];
#pragma unroll
    for (int i = 0; i < 4; i++)
#pragma unroll
        for (int j = 0; j < 4; j++)
#pragma unroll
            for (int r = 0; r < 4; r++) acc[i][j][r] = 0.f;

    auto load_chunk = [&](int c, int b) {
        const int koff = c * GKC;
        const uint32_t dst0 = sbase + b * BUFB;
#pragma unroll
        for (int l = 0; l < 8; l++) {
            int e = tid + l * 256;               // 0..2047
            int arr = e >> 9;                    // 0..3
            int r = (e >> 2) & 127;
            int q = e & 3;
            const __nv_bfloat16* G = (arr == 0) ? Ah : (arr == 1) ? Al
                                   : (arr == 2) ? Bh : Bl;
            int t0 = (arr < 2) ? m0 : n0;
            const __nv_bfloat16* src = G + (size_t)(t0 + r) * HID + koff + q * 8;
            CP_ASYNC16(dst0 + arr * ARRB + r * 80 + q * 16, src);
        }
    };

    load_chunk(0, 0);
    CP_COMMIT();

    for (int c = 0; c < GNC; c++) {
        const int b = c & 1;
        if (c + 1 < GNC) { load_chunk(c + 1, (c + 1) & 1); CP_COMMIT(); CP_WAIT1(); }
        else             { CP_WAIT0(); }
        __syncthreads();

        const uint32_t bufb = sbase + b * BUFB;
        const int arow = (lane & 15);
        const int acolb = ((lane >> 4) * 8) * 2;
        const int brow = ((lane >> 4) << 3) + (lane & 7);
        const int bcolb = (((lane >> 3) & 1) * 8) * 2;

#pragma unroll
        for (int kk = 0; kk < 2; kk++) {
            uint32_t ah[4][4], al[4][4], bh[4][2], bl[4][2];
            const int kb = kk * 32;   // 16 bf16 * 2B
#pragma unroll
            for (int i = 0; i < 4; i++) {
                uint32_t ad = bufb + (m0w + i * 16 + arow) * 80 + acolb + kb;
                LDSM_X4(ah[i][0], ah[i][1], ah[i][2], ah[i][3], ad);
                LDSM_X4(al[i][0], al[i][1], al[i][2], al[i][3], ad + ARRB);
            }
            {
                uint32_t bd = bufb + 2 * ARRB + (n0w + brow) * 80 + bcolb + kb;
                uint32_t r0, r1, r2, r3;
                LDSM_X4(r0, r1, r2, r3, bd);
                bh[0][0] = r0; bh[0][1] = r1; bh[1][0] = r2; bh[1][1] = r3;
                LDSM_X4(r0, r1, r2, r3, bd + 16 * 80);
                bh[2][0] = r0; bh[2][1] = r1; bh[3][0] = r2; bh[3][1] = r3;
                LDSM_X4(r0, r1, r2, r3, bd + ARRB);
                bl[0][0] = r0; bl[0][1] = r1; bl[1][0] = r2; bl[1][1] = r3;
                LDSM_X4(r0, r1, r2, r3, bd + ARRB + 16 * 80);
                bl[2][0] = r0; bl[2][1] = r1; bl[3][0] = r2; bl[3][1] = r3;
            }
#pragma unroll
            for (int i = 0; i < 4; i++)
#pragma unroll
                for (int j = 0; j < 4; j++) {
                    MMA16816(acc[i][j], ah[i], bh[j]);
                    MMA16816(acc[i][j], ah[i], bl[j]);
                    MMA16816(acc[i][j], al[i], bh[j]);
                }
        }
        __syncthreads();
    }

    // epilogue: frags -> SMEM (fp32, pitch EPIP) -> coalesced global
    float* fsm = reinterpret_cast<float*>(dsm);
    const int r0w = m0w + (lane >> 2);
    const int c0w = n0w + (lane & 3) * 2;
#pragma unroll
    for (int i = 0; i < 4; i++)
#pragma unroll
        for (int j = 0; j < 4; j++) {
            int r = r0w + i * 16, cc = c0w + j * 8;
            fsm[r * EPIP + cc]           = acc[i][j][0];
            fsm[r * EPIP + cc + 1]       = acc[i][j][1];
            fsm[(r + 8) * EPIP + cc]     = acc[i][j][2];
            fsm[(r + 8) * EPIP + cc + 1] = acc[i][j][3];
        }
    __syncthreads();
#pragma unroll
    for (int l = 0; l < 64; l++) {
        int e = tid + l * 256;
        int r = e >> 7, cc = e & 127;
        float v = fsm[r * EPIP + cc];
        if (headmajor) {
            int n = n0 + cc;
            C[((size_t)(n >> 6) * S_LEN + m0 + r) * HDIM + (n & 63)] = v;
        } else {
            C[(size_t)(m0 + r) * HID + n0 + cc] = v;
        }
    }
}

// ---------------------------------------------------------------------------
// fast exp
// ---------------------------------------------------------------------------
__device__ __forceinline__ float fexp(float x)
{
    float y = fmaxf(x * 1.4426950408889634f, -110.0f);
    float n = rintf(y);
    float f = y - n;
    float p = 1.3333558146428443e-3f;
    p = fmaf(p, f, 9.618129842071803e-3f);
    p = fmaf(p, f, 5.550410866482158e-2f);
    p = fmaf(p, f, 2.402265069591007e-1f);
    p = fmaf(p, f, 6.931471805599453e-1f);
    p = fmaf(p, f, 1.0f);
    return p * __int_as_float(((int)n + 127) << 23);
}

// ---------------------------------------------------------------------------
// Attention kernel (round-1 version, unchanged — fp32 SIMT, ring semantics)
// ---------------------------------------------------------------------------
#define ATQ  32
#define SP   1025
#define KP   129
#define VP   68
#define KVBUF 8704

__global__ __launch_bounds__(256) void attn_k(const float* __restrict__ Qg,
                                              const float* __restrict__ Kg,
                                              const float* __restrict__ Vg,
                                              float* __restrict__ Aout)
{
    extern __shared__ float sm[];
    float* Ssc = sm;
    float* KVb = Ssc + ATQ * SP;
    float* Qs  = KVb + KVBUF;
    float* dsh = Qs + ATQ * HDIM;

    const int h  = blockIdx.y;
    const int q0 = blockIdx.x * ATQ;
    const int tid = threadIdx.x;

    const float* Qh = Qg + ((size_t)h * S_LEN + q0) * HDIM;
    const float* Kh = Kg + (size_t)h * S_LEN * HDIM;
    const float* Vh = Vg + (size_t)h * S_LEN * HDIM;

#pragma unroll
    for (int l = 0; l < 8; l++) {
        int e = tid + l * 256;
        Qs[e] = Qh[e];
    }
    if (tid < ATQ) dsh[tid] = 0.f;

    const int qg  = tid >> 5;
    const int kt  = tid & 31;
    const int half = tid >> 7;
    const int u   = tid & 127;
    const int dg  = u & 15;
    const int qg2 = u >> 4;
    const int qs  = tid & 31;
    const int s8  = tid >> 5;

    float num[4][4];
#pragma unroll
    for (int i = 0; i < 4; i++)
#pragma unroll
        for (int j = 0; j < 4; j++) num[i][j] = 0.f;

    __syncthreads();

    for (int blk = 0; blk < NBLK; blk++) {
        const float* Kb = Kh + (size_t)blk * KVBLK * HDIM;
        const float* Vb = Vh + (size_t)blk * KVBLK * HDIM;

        for (int c = 0; c < 8; c++) {
            __syncthreads();
#pragma unroll 8
            for (int l = 0; l < 32; l++) {
                int e = tid + l * 256;
                int kk = e >> 6, d = e & 63;
                KVb[d * KP + kk] = Kb[(size_t)(c * 128 + kk) * HDIM + d];
            }
            __syncthreads();

            float acc[4][4];
#pragma unroll
            for (int i = 0; i < 4; i++)
#pragma unroll
                for (int j = 0; j < 4; j++) acc[i][j] = 0.f;

#pragma unroll 4
            for (int d = 0; d < 64; d++) {
                float qv[4], kv[4];
#pragma unroll
                for (int i = 0; i < 4; i++) qv[i] = Qs[(qg * 4 + i) * HDIM + d];
#pragma unroll
                for (int j = 0; j < 4; j++) kv[j] = KVb[d * KP + kt + 32 * j];
#pragma unroll
                for (int i = 0; i < 4; i++)
#pragma unroll
                    for (int j = 0; j < 4; j++)
                        acc[i][j] = fmaf(qv[i], kv[j], acc[i][j]);
            }
#pragma unroll
            for (int i = 0; i < 4; i++)
#pragma unroll
                for (int j = 0; j < 4; j++)
                    Ssc[(qg * 4 + i) * SP + c * 128 + kt + 32 * j] = acc[i][j] * 0.125f;
        }
        __syncthreads();

        {
            float* row = Ssc + qs * SP + s8 * 128;
            float m = -1e30f;
#pragma unroll 8
            for (int i = 0; i < 128; i++) m = fmaxf(m, row[i]);
            KVb[tid] = m;
        }
        __syncthreads();
        if (tid < ATQ) {
            float m = KVb[tid];
#pragma unroll
            for (int s = 1; s < 8; s++) m = fmaxf(m, KVb[tid + 32 * s]);
            KVb[256 + tid] = m;
        }
        __syncthreads();

        {
            float m = KVb[256 + qs];
            float* row = Ssc + qs * SP + s8 * 128;
            float sum = 0.f;
#pragma unroll 4
            for (int i = 0; i < 128; i++) {
                float e = fexp(row[i] - m);
                row[i] = e;
                sum += e;
            }
            KVb[512 + tid] = sum;
        }
        __syncthreads();
        if (tid < ATQ) {
            float s = 0.f;
#pragma unroll
            for (int j = 0; j < 8; j++) s += KVb[512 + tid + 32 * j];
            dsh[tid] += s;
        }

        for (int c = 0; c < 8; c++) {
            __syncthreads();
#pragma unroll 8
            for (int l = 0; l < 32; l++) {
                int e = tid + l * 256;
                int kk = e >> 6, d = e & 63;
                KVb[kk * VP + d] = Vb[(size_t)(c * 128 + kk) * HDIM + d];
            }
            __syncthreads();

            const int kbase = c * 128 + half * 64;
            const float* Srow = Ssc + kbase;
            const float* Vrow = KVb + (half * 64) * VP + dg * 4;
#pragma unroll 4
            for (int kk = 0; kk < 64; kk++) {
                float sv[4], vv[4];
#pragma unroll
                for (int i = 0; i < 4; i++) sv[i] = Srow[(qg2 * 4 + i) * SP + kk];
#pragma unroll
                for (int j = 0; j < 4; j++) vv[j] = Vrow[kk * VP + j];
#pragma unroll
                for (int i = 0; i < 4; i++)
#pragma unroll
                    for (int j = 0; j < 4; j++)
                        num[i][j] = fmaf(sv[i], vv[j], num[i][j]);
            }
        }
    }

    __syncthreads();
    if (half == 1) {
#pragma unroll
        for (int i = 0; i < 4; i++)
#pragma unroll
            for (int j = 0; j < 4; j++)
                Ssc[u * 16 + i * 4 + j] = num[i][j];
    }
    __syncthreads();
    if (half == 0) {
#pragma unroll
        for (int i = 0; i < 4; i++) {
            float inv = 1.0f / dsh[qg2 * 4 + i];
#pragma unroll
            for (int j = 0; j < 4; j++) {
                float v = num[i][j] + Ssc[u * 16 + i * 4 + j];
                Aout[(size_t)(q0 + qg2 * 4 + i) * HID + h * HDIM + dg * 4 + j] = v * inv;
            }
        }
    }
}

// ---------------------------------------------------------------------------
// launch
// ---------------------------------------------------------------------------
extern "C" void kernel_launch(void* const* d_in, const int* in_sizes, int n_in,
                              void* d_out, int out_size)
{
    const float* x   = (const float*)d_in[0];
    const float* w_q = (const float*)d_in[1];
    const float* w_k = (const float*)d_in[2];
    const float* w_v = (const float*)d_in[3];
    const float* w_o = (const float*)d_in[4];
    float* out = (float*)d_out;

    float *Qp, *Kp, *Vp, *Ap;
    cudaGetSymbolAddress((void**)&Qp, g_Q);
    cudaGetSymbolAddress((void**)&Kp, g_K);
    cudaGetSymbolAddress((void**)&Vp, g_V);
    cudaGetSymbolAddress((void**)&Ap, g_A);

    __nv_bfloat16 *Xh, *Xl, *Ahp, *Alp, *Wh, *Wl;
    cudaGetSymbolAddress((void**)&Xh, g_Xhi);
    cudaGetSymbolAddress((void**)&Xl, g_Xlo);
    cudaGetSymbolAddress((void**)&Ahp, g_Ahi);
    cudaGetSymbolAddress((void**)&Alp, g_Alo);
    cudaGetSymbolAddress((void**)&Wh, g_Wh);
    cudaGetSymbolAddress((void**)&Wl, g_Wl);

    const int attn_smem = (ATQ * SP + KVBUF + ATQ * HDIM + ATQ) * sizeof(float);
    cudaFuncSetAttribute(attn_k, cudaFuncAttributeMaxDynamicSharedMemorySize, attn_smem);

    const int gemm_smem = 2 * BUFB;   // 81920 B (also covers 128*EPIP*4 epilogue)
    cudaFuncSetAttribute(gemmmma_k, cudaFuncAttributeMaxDynamicSharedMemorySize, gemm_smem);

    // hi/lo conversions
    convhl_k<<<(S_LEN * HID) / 1024, 256>>>(x, Xh, Xl);
    dim3 wt_grid(HID / 32, HID / 32);
    const float* ws[4] = {w_q, w_k, w_v, w_o};
    for (int i = 0; i < 4; i++)
        convwt_k<<<wt_grid, 256>>>(ws[i], Wh + (size_t)i * HID * HID, Wl + (size_t)i * HID * HID);

    dim3 gg(HID / 128, S_LEN / 128);
    gemmmma_k<<<gg, 256, gemm_smem>>>(Xh, Xl, Wh + 0 * (size_t)HID * HID, Wl + 0 * (size_t)HID * HID, Qp, 1);
    gemmmma_k<<<gg, 256, gemm_smem>>>(Xh, Xl, Wh + 1 * (size_t)HID * HID, Wl + 1 * (size_t)HID * HID, Kp, 1);
    gemmmma_k<<<gg, 256, gemm_smem>>>(Xh, Xl, Wh + 2 * (size_t)HID * HID, Wl + 2 * (size_t)HID * HID, Vp, 1);

    dim3 attn_grid(S_LEN / ATQ, HEADS);
    attn_k<<<attn_grid, 256, attn_smem>>>(Qp, Kp, Vp, Ap);

    convhl_k<<<(S_LEN * HID) / 1024, 256>>>(Ap, Ahp, Alp);
    gemmmma_k<<<gg, 256, gemm_smem>>>(Ahp, Alp, Wh + 3 * (size_t)HID * HID, Wl + 3 * (size_t)HID * HID, out, 0);
}

// round 5
// speedup vs baseline: 2.5672x; 2.5672x over previous
#include <cuda_runtime.h>
#include <cuda_bf16.h>
#include <cstdint>

#define S_LEN 4096
#define HID   1024
#define HEADS 16
#define HDIM  64
#define NBLK  4

__device__ __nv_bfloat16 g_Xh[S_LEN * HID], g_Xl[S_LEN * HID];
__device__ __nv_bfloat16 g_Qh[S_LEN * HID], g_Ql[S_LEN * HID];  // [h][s][d]
__device__ __nv_bfloat16 g_Kh[S_LEN * HID], g_Kl[S_LEN * HID];  // [h][s][d]
__device__ __nv_bfloat16 g_Vh[S_LEN * HID], g_Vl[S_LEN * HID];  // [h][d][s]
__device__ __nv_bfloat16 g_Ah[S_LEN * HID], g_Al[S_LEN * HID];  // [s][hid]
__device__ __nv_bfloat16 g_Wh[4][HID * HID], g_Wl[4][HID * HID];

__device__ __forceinline__ uint32_t smem_u32(const void* p) {
    uint32_t a;
    asm("{ .reg .u64 t; cvta.to.shared.u64 t, %1; cvt.u32.u64 %0, t; }" : "=r"(a) : "l"(p));
    return a;
}
#define CP_ASYNC16(dst, src) \
    asm volatile("cp.async.cg.shared.global [%0], [%1], 16;" :: "r"(dst), "l"(src))
#define CP_COMMIT() asm volatile("cp.async.commit_group;" ::: "memory")
#define CP_WAIT0()  asm volatile("cp.async.wait_group 0;" ::: "memory")
#define CP_WAIT1()  asm volatile("cp.async.wait_group 1;" ::: "memory")
#define LDSM_X4(r0, r1, r2, r3, addr) \
    asm volatile("ldmatrix.sync.aligned.m8n8.x4.shared.b16 {%0,%1,%2,%3}, [%4];" \
                 : "=r"(r0), "=r"(r1), "=r"(r2), "=r"(r3) : "r"(addr))
#define MMA16816(d, a, b) \
    asm volatile("mma.sync.aligned.m16n8k16.row.col.f32.bf16.bf16.f32 " \
                 "{%0,%1,%2,%3}, {%4,%5,%6,%7}, {%8,%9}, {%0,%1,%2,%3};" \
                 : "+f"((d)[0]), "+f"((d)[1]), "+f"((d)[2]), "+f"((d)[3]) \
                 : "r"((a)[0]), "r"((a)[1]), "r"((a)[2]), "r"((a)[3]), \
                   "r"((b)[0]), "r"((b)[1]))

__device__ __forceinline__ uint32_t packbf2(float lo, float hi) {
    uint32_t r;
    asm("cvt.rn.bf16x2.f32 %0, %1, %2;" : "=r"(r) : "f"(hi), "f"(lo));
    return r;
}
__device__ __forceinline__ float bflow(uint32_t p)  { return __uint_as_float(p << 16); }
__device__ __forceinline__ float bfhigh(uint32_t p) { return __uint_as_float(p & 0xffff0000u); }
__device__ __forceinline__ uint32_t exppack(float s, float m, float& den) {
    float e;
    asm("ex2.approx.f32 %0, %1;" : "=f"(e) : "f"((s - m) * 1.4426950408889634f));
    den += e;
    uint32_t hb = (uint32_t)__bfloat16_as_ushort(__float2bfloat16(e));
    uint32_t lb = (uint32_t)__bfloat16_as_ushort(__float2bfloat16(e - __uint_as_float(hb << 16)));
    return (lb << 16) | hb;
}

// ---------------- conversions ----------------
__global__ __launch_bounds__(256) void convhl_k(const float* __restrict__ X,
                                                __nv_bfloat16* __restrict__ H,
                                                __nv_bfloat16* __restrict__ L)
{
    int i = (blockIdx.x * 256 + threadIdx.x) * 4;
    float4 v = *reinterpret_cast<const float4*>(X + i);
    float f[4] = {v.x, v.y, v.z, v.w};
    __nv_bfloat16 h[4], l[4];
#pragma unroll
    for (int j = 0; j < 4; j++) {
        h[j] = __float2bfloat16(f[j]);
        l[j] = __float2bfloat16(f[j] - __bfloat162float(h[j]));
    }
    *reinterpret_cast<uint2*>(H + i) = *reinterpret_cast<uint2*>(h);
    *reinterpret_cast<uint2*>(L + i) = *reinterpret_cast<uint2*>(l);
}

__global__ __launch_bounds__(256) void convwt_k(const float* __restrict__ W,
                                                __nv_bfloat16* __restrict__ Ht,
                                                __nv_bfloat16* __restrict__ Lt)
{
    __shared__ float t[32][33];
    int n0 = blockIdx.x * 32, k0 = blockIdx.y * 32;
    int tx = threadIdx.x & 31, ty = threadIdx.x >> 5;
#pragma unroll
    for (int s = 0; s < 32; s += 8)
        t[ty + s][tx] = W[(size_t)(k0 + ty + s) * HID + n0 + tx];
    __syncthreads();
#pragma unroll
    for (int s = 0; s < 32; s += 8) {
        float v = t[tx][ty + s];
        __nv_bfloat16 h = __float2bfloat16(v);
        __nv_bfloat16 l = __float2bfloat16(v - __bfloat162float(h));
        size_t o = (size_t)(n0 + ty + s) * HID + k0 + tx;
        Ht[o] = h; Lt[o] = l;
    }
}

// ---------------- HMMA 3-term GEMM ----------------
// mode 0: C fp32 [m][HID]; mode 1: H/L bf16 [h][s][d]; mode 2: H/L bf16 [h][d][s]
#define GKC  32
#define GNC  (HID / GKC)
#define ARRB (128 * 80)
#define BUFB (4 * ARRB)
#define EPIP 129

__global__ __launch_bounds__(256) void gemmmma_k(const __nv_bfloat16* __restrict__ Ap,
                                                 const __nv_bfloat16* __restrict__ Alp,
                                                 const __nv_bfloat16* __restrict__ Bp,
                                                 const __nv_bfloat16* __restrict__ Blp,
                                                 float* __restrict__ C,
                                                 __nv_bfloat16* __restrict__ H,
                                                 __nv_bfloat16* __restrict__ L,
                                                 int mode)
{
    extern __shared__ char dsm[];
    const uint32_t sbase = smem_u32(dsm);
    const int tid = threadIdx.x, wid = tid >> 5, lane = tid & 31;
    const int m0 = blockIdx.y * 128, n0 = blockIdx.x * 128;
    const int m0w = (wid & 1) * 64, n0w = (wid >> 1) * 32;

    float acc[4][4][4];
#pragma unroll
    for (int i = 0; i < 4; i++)
#pragma unroll
        for (int j = 0; j < 4; j++)
#pragma unroll
            for (int r = 0; r < 4; r++) acc[i][j][r] = 0.f;

    auto load_chunk = [&](int c, int b) {
        const int koff = c * GKC;
        const uint32_t dst0 = sbase + b * BUFB;
#pragma unroll
        for (int l = 0; l < 8; l++) {
            int e = tid + l * 256;
            int arr = e >> 9, r = (e >> 2) & 127, q = e & 3;
            const __nv_bfloat16* G = (arr == 0) ? Ap : (arr == 1) ? Alp
                                   : (arr == 2) ? Bp : Blp;
            int t0 = (arr < 2) ? m0 : n0;
            CP_ASYNC16(dst0 + arr * ARRB + r * 80 + q * 16,
                       G + (size_t)(t0 + r) * HID + koff + q * 8);
        }
    };

    load_chunk(0, 0);
    CP_COMMIT();

    for (int c = 0; c < GNC; c++) {
        const int b = c & 1;
        if (c + 1 < GNC) { load_chunk(c + 1, (c + 1) & 1); CP_COMMIT(); CP_WAIT1(); }
        else             { CP_WAIT0(); }
        __syncthreads();

        const uint32_t bufb = sbase + b * BUFB;
        const int arow = lane & 15, acolb = (lane >> 4) * 16;
        const int brow = ((lane >> 4) << 3) + (lane & 7);
        const int bcolb = ((lane >> 3) & 1) * 16;

#pragma unroll
        for (int kk = 0; kk < 2; kk++) {
            uint32_t ah[4][4], al[4][4], bh[4][2], bl[4][2];
            const int kb = kk * 32;
#pragma unroll
            for (int i = 0; i < 4; i++) {
                uint32_t ad = bufb + (m0w + i * 16 + arow) * 80 + acolb + kb;
                LDSM_X4(ah[i][0], ah[i][1], ah[i][2], ah[i][3], ad);
                LDSM_X4(al[i][0], al[i][1], al[i][2], al[i][3], ad + ARRB);
            }
            {
                uint32_t bd = bufb + 2 * ARRB + (n0w + brow) * 80 + bcolb + kb;
                uint32_t r0, r1, r2, r3;
                LDSM_X4(r0, r1, r2, r3, bd);
                bh[0][0] = r0; bh[0][1] = r1; bh[1][0] = r2; bh[1][1] = r3;
                LDSM_X4(r0, r1, r2, r3, bd + 16 * 80);
                bh[2][0] = r0; bh[2][1] = r1; bh[3][0] = r2; bh[3][1] = r3;
                LDSM_X4(r0, r1, r2, r3, bd + ARRB);
                bl[0][0] = r0; bl[0][1] = r1; bl[1][0] = r2; bl[1][1] = r3;
                LDSM_X4(r0, r1, r2, r3, bd + ARRB + 16 * 80);
                bl[2][0] = r0; bl[2][1] = r1; bl[3][0] = r2; bl[3][1] = r3;
            }
#pragma unroll
            for (int i = 0; i < 4; i++)
#pragma unroll
                for (int j = 0; j < 4; j++) {
                    MMA16816(acc[i][j], ah[i], bh[j]);
                    MMA16816(acc[i][j], ah[i], bl[j]);
                    MMA16816(acc[i][j], al[i], bh[j]);
                }
        }
        __syncthreads();
    }

    float* fsm = reinterpret_cast<float*>(dsm);
    const int r0w = m0w + (lane >> 2), c0w = n0w + (lane & 3) * 2;
#pragma unroll
    for (int i = 0; i < 4; i++)
#pragma unroll
        for (int j = 0; j < 4; j++) {
            int r = r0w + i * 16, cc = c0w + j * 8;
            fsm[r * EPIP + cc]           = acc[i][j][0];
            fsm[r * EPIP + cc + 1]       = acc[i][j][1];
            fsm[(r + 8) * EPIP + cc]     = acc[i][j][2];
            fsm[(r + 8) * EPIP + cc + 1] = acc[i][j][3];
        }
    __syncthreads();

    if (mode == 0) {
#pragma unroll
        for (int l = 0; l < 64; l++) {
            int e = tid + l * 256;
            int r = e >> 7, cc = e & 127;
            C[(size_t)(m0 + r) * HID + n0 + cc] = fsm[r * EPIP + cc];
        }
    } else if (mode == 1) {
#pragma unroll
        for (int l = 0; l < 32; l++) {
            int e = tid + l * 256;
            int r = e >> 6, c2 = (e & 63) * 2;
            float f0 = fsm[r * EPIP + c2], f1 = fsm[r * EPIP + c2 + 1];
            uint32_t hp = packbf2(f0, f1);
            uint32_t lp = packbf2(f0 - bflow(hp), f1 - bfhigh(hp));
            int n = n0 + c2;
            size_t o = ((size_t)(n >> 6) * S_LEN + m0 + r) * HDIM + (n & 63);
            *reinterpret_cast<uint32_t*>(H + o) = hp;
            *reinterpret_cast<uint32_t*>(L + o) = lp;
        }
    } else {
#pragma unroll
        for (int l = 0; l < 32; l++) {
            int e = tid + l * 256;
            int cc = e >> 6, rp = (e & 63) * 2;
            float f0 = fsm[rp * EPIP + cc], f1 = fsm[(rp + 1) * EPIP + cc];
            uint32_t hp = packbf2(f0, f1);
            uint32_t lp = packbf2(f0 - bflow(hp), f1 - bfhigh(hp));
            int n = n0 + cc;
            size_t o = ((size_t)(n >> 6) * HDIM + (n & 63)) * S_LEN + m0 + rp;
            *reinterpret_cast<uint32_t*>(H + o) = hp;
            *reinterpret_cast<uint32_t*>(L + o) = lp;
        }
    }
}

// ---------------- HMMA ring attention ----------------
#define AQ      32
#define EP      1032
#define EBYTES  (AQ * EP * 4)
#define KPITCH  144
#define VPITCH  272
#define KTILE   (128 * KPITCH)
#define QPITCH  144
#define OFF_KBUF EBYTES
#define OFF_Q    (OFF_KBUF + 4 * KTILE)
#define OFF_DSH  (OFF_Q + 2 * 32 * QPITCH)
#define ASMEM    (OFF_DSH + 128)

__global__ __launch_bounds__(256) void attn2_k(
    const __nv_bfloat16* __restrict__ Qh, const __nv_bfloat16* __restrict__ Ql,
    const __nv_bfloat16* __restrict__ Kh, const __nv_bfloat16* __restrict__ Kl,
    const __nv_bfloat16* __restrict__ Vh, const __nv_bfloat16* __restrict__ Vl,
    __nv_bfloat16* __restrict__ Oh, __nv_bfloat16* __restrict__ Ol)
{
    extern __shared__ char smraw[];
    float* Eb = reinterpret_cast<float*>(smraw);
    float* dsh = reinterpret_cast<float*>(smraw + OFF_DSH);
    const uint32_t sb = smem_u32(smraw);

    const int tid = threadIdx.x, wid = tid >> 5, lane = tid & 31;
    const int g = lane >> 2, tg = lane & 3;
    const int h = blockIdx.y, q0 = blockIdx.x * AQ;

    if (tid < 32) dsh[tid] = 0.f;
    {
        int r = tid >> 3, q = tid & 7;
        const size_t go = ((size_t)h * S_LEN + q0 + r) * HDIM + q * 8;
        CP_ASYNC16(sb + OFF_Q + r * QPITCH + q * 16, Qh + go);
        CP_ASYNC16(sb + OFF_Q + 32 * QPITCH + r * QPITCH + q * 16, Ql + go);
    }
    CP_COMMIT(); CP_WAIT0();
    __syncthreads();

    uint32_t qfh[2][4][4], qfl[2][4][4];
    {
        int rA = lane & 15, cb = (lane >> 4) * 16;
#pragma unroll
        for (int mt = 0; mt < 2; mt++)
#pragma unroll
            for (int kt = 0; kt < 4; kt++) {
                uint32_t a = sb + OFF_Q + (mt * 16 + rA) * QPITCH + kt * 32 + cb;
                LDSM_X4(qfh[mt][kt][0], qfh[mt][kt][1], qfh[mt][kt][2], qfh[mt][kt][3], a);
                LDSM_X4(qfl[mt][kt][0], qfl[mt][kt][1], qfl[mt][kt][2], qfl[mt][kt][3],
                        a + 32 * QPITCH);
            }
    }

    float num[2][4];
#pragma unroll
    for (int n = 0; n < 2; n++)
#pragma unroll
        for (int r = 0; r < 4; r++) num[n][r] = 0.f;

    const int mtv = wid >> 2, np = wid & 3;

    auto stageK = [&](int blk, int c, int b) {
        const uint32_t dst = sb + OFF_KBUF + b * 2 * KTILE;
        const size_t base = ((size_t)h * S_LEN + blk * 1024 + c * 128) * HDIM;
#pragma unroll
        for (int i = 0; i < 4; i++) {
            int e = tid + i * 256;
            int r = e >> 3, q = e & 7;
            CP_ASYNC16(dst + r * KPITCH + q * 16, Kh + base + (size_t)r * HDIM + q * 8);
            CP_ASYNC16(dst + KTILE + r * KPITCH + q * 16, Kl + base + (size_t)r * HDIM + q * 8);
        }
    };
    auto stageV = [&](int blk, int c, int b) {
        const uint32_t dst = sb + OFF_KBUF + b * 2 * KTILE;
        const size_t base = (size_t)h * HDIM * S_LEN + blk * 1024 + c * 128;
#pragma unroll
        for (int i = 0; i < 4; i++) {
            int e = tid + i * 256;
            int r = e >> 4, q = e & 15;
            CP_ASYNC16(dst + r * VPITCH + q * 16, Vh + base + (size_t)r * S_LEN + q * 8);
            CP_ASYNC16(dst + KTILE + r * VPITCH + q * 16, Vl + base + (size_t)r * S_LEN + q * 8);
        }
    };

    for (int blk = 0; blk < NBLK; blk++) {
        stageK(blk, 0, 0); CP_COMMIT();
        for (int c = 0; c < 8; c++) {
            __syncthreads();
            if (c < 7) { stageK(blk, c + 1, (c + 1) & 1); CP_COMMIT(); CP_WAIT1(); }
            else       { CP_WAIT0(); }
            __syncthreads();

            const uint32_t kb = sb + OFF_KBUF + (c & 1) * 2 * KTILE;
            const int rB = wid * 16 + ((lane >> 4) & 1) * 8 + (lane & 7);
            const int cB = ((lane >> 3) & 1) * 16;

            float acc[2][2][4];
#pragma unroll
            for (int mt = 0; mt < 2; mt++)
#pragma unroll
                for (int nt = 0; nt < 2; nt++)
#pragma unroll
                    for (int r = 0; r < 4; r++) acc[mt][nt][r] = 0.f;

#pragma unroll
            for (int kt = 0; kt < 4; kt++) {
                uint32_t bh[4], bl[4];
                uint32_t ad = kb + rB * KPITCH + kt * 32 + cB;
                LDSM_X4(bh[0], bh[1], bh[2], bh[3], ad);
                LDSM_X4(bl[0], bl[1], bl[2], bl[3], ad + KTILE);
#pragma unroll
                for (int mt = 0; mt < 2; mt++)
#pragma unroll
                    for (int nt = 0; nt < 2; nt++) {
                        MMA16816(acc[mt][nt], qfh[mt][kt], &bh[nt * 2]);
                        MMA16816(acc[mt][nt], qfh[mt][kt], &bl[nt * 2]);
                        MMA16816(acc[mt][nt], qfl[mt][kt], &bh[nt * 2]);
                    }
            }
#pragma unroll
            for (int mt = 0; mt < 2; mt++)
#pragma unroll
                for (int nt = 0; nt < 2; nt++) {
                    int row = mt * 16 + g;
                    int col = c * 128 + wid * 16 + nt * 8 + tg * 2;
                    *reinterpret_cast<float2*>(Eb + row * EP + col) =
                        make_float2(acc[mt][nt][0] * 0.125f, acc[mt][nt][1] * 0.125f);
                    *reinterpret_cast<float2*>(Eb + (row + 8) * EP + col) =
                        make_float2(acc[mt][nt][2] * 0.125f, acc[mt][nt][3] * 0.125f);
                }
        }
        __syncthreads();

        stageV(blk, 0, 0); CP_COMMIT();

#pragma unroll
        for (int rr = 0; rr < 4; rr++) {
            const int row = wid * 4 + rr;
            float4* rp = reinterpret_cast<float4*>(Eb + row * EP);
            float4 v[8];
            float m = -1e30f;
#pragma unroll
            for (int i = 0; i < 8; i++) {
                v[i] = rp[lane + 32 * i];
                m = fmaxf(m, fmaxf(fmaxf(v[i].x, v[i].y), fmaxf(v[i].z, v[i].w)));
            }
#pragma unroll
            for (int off = 16; off >= 1; off >>= 1)
                m = fmaxf(m, __shfl_xor_sync(0xffffffffu, m, off));
            float den = 0.f;
#pragma unroll
            for (int i = 0; i < 8; i++) {
                uint4 pk;
                pk.x = exppack(v[i].x, m, den);
                pk.y = exppack(v[i].y, m, den);
                pk.z = exppack(v[i].z, m, den);
                pk.w = exppack(v[i].w, m, den);
                reinterpret_cast<uint4*>(rp)[lane + 32 * i] = pk;
            }
#pragma unroll
            for (int off = 16; off >= 1; off >>= 1)
                den += __shfl_xor_sync(0xffffffffu, den, off);
            if (lane == 0) dsh[row] += den;
        }

        for (int c = 0; c < 8; c++) {
            __syncthreads();
            if (c < 7) { stageV(blk, c + 1, (c + 1) & 1); CP_COMMIT(); CP_WAIT1(); }
            else       { CP_WAIT0(); }
            __syncthreads();

            const uint32_t vb = sb + OFF_KBUF + (c & 1) * 2 * KTILE;
            const int rB = np * 16 + ((lane >> 4) & 1) * 8 + (lane & 7);
            const int cB = ((lane >> 3) & 1) * 16;
            const int r0 = mtv * 16 + g;

#pragma unroll
            for (int u = 0; u < 8; u++) {
                const int kbase = c * 128 + u * 16;
                uint2 wA = *reinterpret_cast<uint2*>(Eb + r0 * EP + kbase + tg * 2);
                uint2 wB = *reinterpret_cast<uint2*>(Eb + r0 * EP + kbase + 8 + tg * 2);
                uint2 wC = *reinterpret_cast<uint2*>(Eb + (r0 + 8) * EP + kbase + tg * 2);
                uint2 wD = *reinterpret_cast<uint2*>(Eb + (r0 + 8) * EP + kbase + 8 + tg * 2);
                uint32_t aH[4] = { __byte_perm(wA.x, wA.y, 0x5410),
                                   __byte_perm(wC.x, wC.y, 0x5410),
                                   __byte_perm(wB.x, wB.y, 0x5410),
                                   __byte_perm(wD.x, wD.y, 0x5410) };
                uint32_t aL[4] = { __byte_perm(wA.x, wA.y, 0x7632),
                                   __byte_perm(wC.x, wC.y, 0x7632),
                                   __byte_perm(wB.x, wB.y, 0x7632),
                                   __byte_perm(wD.x, wD.y, 0x7632) };
                uint32_t bh[4], bl[4];
                uint32_t ad = vb + rB * VPITCH + u * 32 + cB;
                LDSM_X4(bh[0], bh[1], bh[2], bh[3], ad);
                LDSM_X4(bl[0], bl[1], bl[2], bl[3], ad + KTILE);
                MMA16816(num[0], aH, &bh[0]);
                MMA16816(num[0], aH, &bl[0]);
                MMA16816(num[0], aL, &bh[0]);
                MMA16816(num[1], aH, &bh[2]);
                MMA16816(num[1], aH, &bl[2]);
                MMA16816(num[1], aL, &bh[2]);
            }
        }
        __syncthreads();
    }

    {
        const int r0 = mtv * 16 + g;
        const float id0 = 1.0f / dsh[r0];
        const float id1 = 1.0f / dsh[r0 + 8];
#pragma unroll
        for (int nt = 0; nt < 2; nt++) {
            const int col = h * HDIM + np * 16 + nt * 8 + tg * 2;
            float o0 = num[nt][0] * id0, o1 = num[nt][1] * id0;
            float o2 = num[nt][2] * id1, o3 = num[nt][3] * id1;
            uint32_t hp0 = packbf2(o0, o1);
            uint32_t lp0 = packbf2(o0 - bflow(hp0), o1 - bfhigh(hp0));
            uint32_t hp1 = packbf2(o2, o3);
            uint32_t lp1 = packbf2(o2 - bflow(hp1), o3 - bfhigh(hp1));
            size_t a0 = (size_t)(q0 + r0) * HID + col;
            size_t a1 = (size_t)(q0 + r0 + 8) * HID + col;
            *reinterpret_cast<uint32_t*>(Oh + a0) = hp0;
            *reinterpret_cast<uint32_t*>(Ol + a0) = lp0;
            *reinterpret_cast<uint32_t*>(Oh + a1) = hp1;
            *reinterpret_cast<uint32_t*>(Ol + a1) = lp1;
        }
    }
}

// ---------------- launch ----------------
extern "C" void kernel_launch(void* const* d_in, const int* in_sizes, int n_in,
                              void* d_out, int out_size)
{
    const float* x   = (const float*)d_in[0];
    const float* ws[4] = {(const float*)d_in[1], (const float*)d_in[2],
                          (const float*)d_in[3], (const float*)d_in[4]};
    float* out = (float*)d_out;

    __nv_bfloat16 *Xh, *Xl, *Qh, *Ql, *Kh, *Kl, *Vh, *Vl, *Ah, *Al, *Wh, *Wl;
    cudaGetSymbolAddress((void**)&Xh, g_Xh); cudaGetSymbolAddress((void**)&Xl, g_Xl);
    cudaGetSymbolAddress((void**)&Qh, g_Qh); cudaGetSymbolAddress((void**)&Ql, g_Ql);
    cudaGetSymbolAddress((void**)&Kh, g_Kh); cudaGetSymbolAddress((void**)&Kl, g_Kl);
    cudaGetSymbolAddress((void**)&Vh, g_Vh); cudaGetSymbolAddress((void**)&Vl, g_Vl);
    cudaGetSymbolAddress((void**)&Ah, g_Ah); cudaGetSymbolAddress((void**)&Al, g_Al);
    cudaGetSymbolAddress((void**)&Wh, g_Wh); cudaGetSymbolAddress((void**)&Wl, g_Wl);

    const int gemm_smem = 2 * BUFB;
    cudaFuncSetAttribute(gemmmma_k, cudaFuncAttributeMaxDynamicSharedMemorySize, gemm_smem);
    cudaFuncSetAttribute(attn2_k, cudaFuncAttributeMaxDynamicSharedMemorySize, ASMEM);

    convhl_k<<<(S_LEN * HID) / 1024, 256>>>(x, Xh, Xl);
    dim3 wt_grid(HID / 32, HID / 32);
    for (int i = 0; i < 4; i++)
        convwt_k<<<wt_grid, 256>>>(ws[i], Wh + (size_t)i * HID * HID, Wl + (size_t)i * HID * HID);

    dim3 gg(HID / 128, S_LEN / 128);
    gemmmma_k<<<gg, 256, gemm_smem>>>(Xh, Xl, Wh, Wl, nullptr, Qh, Ql, 1);
    gemmmma_k<<<gg, 256, gemm_smem>>>(Xh, Xl, Wh + (size_t)HID * HID, Wl + (size_t)HID * HID,
                                      nullptr, Kh, Kl, 1);
    gemmmma_k<<<gg, 256, gemm_smem>>>(Xh, Xl, Wh + 2 * (size_t)HID * HID, Wl + 2 * (size_t)HID * HID,
                                      nullptr, Vh, Vl, 2);

    dim3 ag(S_LEN / AQ, HEADS);
    attn2_k<<<ag, 256, ASMEM>>>(Qh, Ql, Kh, Kl, Vh, Vl, Ah, Al);

    gemmmma_k<<<gg, 256, gemm_smem>>>(Ah, Al, Wh + 3 * (size_t)HID * HID, Wl + 3 * (size_t)HID * HID,
                                      out, nullptr, nullptr, 0);
}

// round 7
// speedup vs baseline: 3.0268x; 1.1790x over previous
#include <cuda_runtime.h>
#include <cuda_bf16.h>
#include <cstdint>

#define S_LEN 4096
#define HID   1024
#define HEADS 16
#define HDIM  64
#define NBLK  4

__device__ __nv_bfloat16 g_Xh[S_LEN * HID], g_Xl[S_LEN * HID];
__device__ __nv_bfloat16 g_Qh[S_LEN * HID], g_Ql[S_LEN * HID];  // [h][s][d]
__device__ __nv_bfloat16 g_Kh[S_LEN * HID], g_Kl[S_LEN * HID];  // [h][s][d] (Kl unused by attn)
__device__ __nv_bfloat16 g_Vh[S_LEN * HID], g_Vl[S_LEN * HID];  // [h][d][s]
__device__ __nv_bfloat16 g_Ah[S_LEN * HID], g_Al[S_LEN * HID];  // [s][hid]
__device__ __nv_bfloat16 g_Wh[4][HID * HID], g_Wl[4][HID * HID];

__device__ __forceinline__ uint32_t smem_u32(const void* p) {
    uint32_t a;
    asm("{ .reg .u64 t; cvta.to.shared.u64 t, %1; cvt.u32.u64 %0, t; }" : "=r"(a) : "l"(p));
    return a;
}
#define CP_ASYNC16(dst, src) \
    asm volatile("cp.async.cg.shared.global [%0], [%1], 16;" :: "r"(dst), "l"(src))
#define CP_COMMIT() asm volatile("cp.async.commit_group;" ::: "memory")
#define CP_WAIT0()  asm volatile("cp.async.wait_group 0;" ::: "memory")
#define CP_WAIT1()  asm volatile("cp.async.wait_group 1;" ::: "memory")
#define LDSM_X4(r0, r1, r2, r3, addr) \
    asm volatile("ldmatrix.sync.aligned.m8n8.x4.shared.b16 {%0,%1,%2,%3}, [%4];" \
                 : "=r"(r0), "=r"(r1), "=r"(r2), "=r"(r3) : "r"(addr))
#define MMA16816(d, a, b) \
    asm volatile("mma.sync.aligned.m16n8k16.row.col.f32.bf16.bf16.f32 " \
                 "{%0,%1,%2,%3}, {%4,%5,%6,%7}, {%8,%9}, {%0,%1,%2,%3};" \
                 : "+f"((d)[0]), "+f"((d)[1]), "+f"((d)[2]), "+f"((d)[3]) \
                 : "r"((a)[0]), "r"((a)[1]), "r"((a)[2]), "r"((a)[3]), \
                   "r"((b)[0]), "r"((b)[1]))

// pack two floats as bf16x2: low halfword = bf16(a), high = bf16(b)
__device__ __forceinline__ uint32_t packbf2(float a, float b) {
    uint32_t r;
    asm("cvt.rn.bf16x2.f32 %0, %1, %2;" : "=r"(r) : "f"(b), "f"(a));
    return r;
}
__device__ __forceinline__ float bflow(uint32_t p)  { return __uint_as_float(p << 16); }
__device__ __forceinline__ float bfhigh(uint32_t p) { return __uint_as_float(p & 0xffff0000u); }
// pack score s as (lo half = bf16(s), hi half = bf16 residual)
__device__ __forceinline__ uint32_t packsc(float s) {
    float hf = __bfloat162float(__float2bfloat16(s));
    return packbf2(s, s - hf);
}
__device__ __forceinline__ float fex2(float x) {
    float e;
    asm("ex2.approx.f32 %0, %1;" : "=f"(e) : "f"(x));
    return e;
}

// ---------------- conversions ----------------
__global__ __launch_bounds__(256) void convhl_k(const float* __restrict__ X,
                                                __nv_bfloat16* __restrict__ H,
                                                __nv_bfloat16* __restrict__ L)
{
    int i = (blockIdx.x * 256 + threadIdx.x) * 4;
    float4 v = *reinterpret_cast<const float4*>(X + i);
    float f[4] = {v.x, v.y, v.z, v.w};
    __nv_bfloat16 h[4], l[4];
#pragma unroll
    for (int j = 0; j < 4; j++) {
        h[j] = __float2bfloat16(f[j]);
        l[j] = __float2bfloat16(f[j] - __bfloat162float(h[j]));
    }
    *reinterpret_cast<uint2*>(H + i) = *reinterpret_cast<uint2*>(h);
    *reinterpret_cast<uint2*>(L + i) = *reinterpret_cast<uint2*>(l);
}

// one launch for all 4 weights (z selects)
__global__ __launch_bounds__(256) void convwt_k(const float* __restrict__ w0,
                                                const float* __restrict__ w1,
                                                const float* __restrict__ w2,
                                                const float* __restrict__ w3,
                                                __nv_bfloat16* __restrict__ HtB,
                                                __nv_bfloat16* __restrict__ LtB)
{
    __shared__ float t[32][33];
    const int z = blockIdx.z;
    const float* W = (z == 0) ? w0 : (z == 1) ? w1 : (z == 2) ? w2 : w3;
    __nv_bfloat16* Ht = HtB + (size_t)z * HID * HID;
    __nv_bfloat16* Lt = LtB + (size_t)z * HID * HID;
    int n0 = blockIdx.x * 32, k0 = blockIdx.y * 32;
    int tx = threadIdx.x & 31, ty = threadIdx.x >> 5;
#pragma unroll
    for (int s = 0; s < 32; s += 8)
        t[ty + s][tx] = W[(size_t)(k0 + ty + s) * HID + n0 + tx];
    __syncthreads();
#pragma unroll
    for (int s = 0; s < 32; s += 8) {
        float v = t[tx][ty + s];
        __nv_bfloat16 h = __float2bfloat16(v);
        __nv_bfloat16 l = __float2bfloat16(v - __bfloat162float(h));
        size_t o = (size_t)(n0 + ty + s) * HID + k0 + tx;
        Ht[o] = h; Lt[o] = l;
    }
}

// ---------------- HMMA 3-term GEMM ----------------
// mode 0: C fp32 [m][HID]; mode 1: H/L bf16 [h][s][d]; mode 2: H/L bf16 [h][d][s]
#define GKC  32
#define GNC  (HID / GKC)
#define ARRB (128 * 80)
#define BUFB (4 * ARRB)
#define EPIP 129

__global__ __launch_bounds__(256) void gemmmma_k(const __nv_bfloat16* __restrict__ Ap,
                                                 const __nv_bfloat16* __restrict__ Alp,
                                                 const __nv_bfloat16* __restrict__ Bp,
                                                 const __nv_bfloat16* __restrict__ Blp,
                                                 float* __restrict__ C,
                                                 __nv_bfloat16* __restrict__ H,
                                                 __nv_bfloat16* __restrict__ L,
                                                 int mode)
{
    extern __shared__ char dsm[];
    const uint32_t sbase = smem_u32(dsm);
    const int tid = threadIdx.x, wid = tid >> 5, lane = tid & 31;
    const int m0 = blockIdx.y * 128, n0 = blockIdx.x * 128;
    const int m0w = (wid & 1) * 64, n0w = (wid >> 1) * 32;

    float acc[4][4][4];
#pragma unroll
    for (int i = 0; i < 4; i++)
#pragma unroll
        for (int j = 0; j < 4; j++)
#pragma unroll
            for (int r = 0; r < 4; r++) acc[i][j][r] = 0.f;

    auto load_chunk = [&](int c, int b) {
        const int koff = c * GKC;
        const uint32_t dst0 = sbase + b * BUFB;
#pragma unroll
        for (int l = 0; l < 8; l++) {
            int e = tid + l * 256;
            int arr = e >> 9, r = (e >> 2) & 127, q = e & 3;
            const __nv_bfloat16* G = (arr == 0) ? Ap : (arr == 1) ? Alp
                                   : (arr == 2) ? Bp : Blp;
            int t0 = (arr < 2) ? m0 : n0;
            CP_ASYNC16(dst0 + arr * ARRB + r * 80 + q * 16,
                       G + (size_t)(t0 + r) * HID + koff + q * 8);
        }
    };

    load_chunk(0, 0);
    CP_COMMIT();

    for (int c = 0; c < GNC; c++) {
        const int b = c & 1;
        if (c + 1 < GNC) { load_chunk(c + 1, (c + 1) & 1); CP_COMMIT(); CP_WAIT1(); }
        else             { CP_WAIT0(); }
        __syncthreads();

        const uint32_t bufb = sbase + b * BUFB;
        const int arow = lane & 15, acolb = (lane >> 4) * 16;
        const int brow = ((lane >> 4) << 3) + (lane & 7);
        const int bcolb = ((lane >> 3) & 1) * 16;

#pragma unroll
        for (int kk = 0; kk < 2; kk++) {
            uint32_t ah[4][4], al[4][4], bh[4][2], bl[4][2];
            const int kb = kk * 32;
#pragma unroll
            for (int i = 0; i < 4; i++) {
                uint32_t ad = bufb + (m0w + i * 16 + arow) * 80 + acolb + kb;
                LDSM_X4(ah[i][0], ah[i][1], ah[i][2], ah[i][3], ad);
                LDSM_X4(al[i][0], al[i][1], al[i][2], al[i][3], ad + ARRB);
            }
            {
                uint32_t bd = bufb + 2 * ARRB + (n0w + brow) * 80 + bcolb + kb;
                uint32_t r0, r1, r2, r3;
                LDSM_X4(r0, r1, r2, r3, bd);
                bh[0][0] = r0; bh[0][1] = r1; bh[1][0] = r2; bh[1][1] = r3;
                LDSM_X4(r0, r1, r2, r3, bd + 16 * 80);
                bh[2][0] = r0; bh[2][1] = r1; bh[3][0] = r2; bh[3][1] = r3;
                LDSM_X4(r0, r1, r2, r3, bd + ARRB);
                bl[0][0] = r0; bl[0][1] = r1; bl[1][0] = r2; bl[1][1] = r3;
                LDSM_X4(r0, r1, r2, r3, bd + ARRB + 16 * 80);
                bl[2][0] = r0; bl[2][1] = r1; bl[3][0] = r2; bl[3][1] = r3;
            }
#pragma unroll
            for (int i = 0; i < 4; i++)
#pragma unroll
                for (int j = 0; j < 4; j++) {
                    MMA16816(acc[i][j], ah[i], bh[j]);
                    MMA16816(acc[i][j], ah[i], bl[j]);
                    MMA16816(acc[i][j], al[i], bh[j]);
                }
        }
        __syncthreads();
    }

    float* fsm = reinterpret_cast<float*>(dsm);
    const int r0w = m0w + (lane >> 2), c0w = n0w + (lane & 3) * 2;
#pragma unroll
    for (int i = 0; i < 4; i++)
#pragma unroll
        for (int j = 0; j < 4; j++) {
            int r = r0w + i * 16, cc = c0w + j * 8;
            fsm[r * EPIP + cc]           = acc[i][j][0];
            fsm[r * EPIP + cc + 1]       = acc[i][j][1];
            fsm[(r + 8) * EPIP + cc]     = acc[i][j][2];
            fsm[(r + 8) * EPIP + cc + 1] = acc[i][j][3];
        }
    __syncthreads();

    if (mode == 0) {
#pragma unroll
        for (int l = 0; l < 64; l++) {
            int e = tid + l * 256;
            int r = e >> 7, cc = e & 127;
            C[(size_t)(m0 + r) * HID + n0 + cc] = fsm[r * EPIP + cc];
        }
    } else if (mode == 1) {
#pragma unroll
        for (int l = 0; l < 32; l++) {
            int e = tid + l * 256;
            int r = e >> 6, c2 = (e & 63) * 2;
            float f0 = fsm[r * EPIP + c2], f1 = fsm[r * EPIP + c2 + 1];
            uint32_t hp = packbf2(f0, f1);
            uint32_t lp = packbf2(f0 - bflow(hp), f1 - bfhigh(hp));
            int n = n0 + c2;
            size_t o = ((size_t)(n >> 6) * S_LEN + m0 + r) * HDIM + (n & 63);
            *reinterpret_cast<uint32_t*>(H + o) = hp;
            *reinterpret_cast<uint32_t*>(L + o) = lp;
        }
    } else {
#pragma unroll
        for (int l = 0; l < 32; l++) {
            int e = tid + l * 256;
            int cc = e >> 6, rp = (e & 63) * 2;
            float f0 = fsm[rp * EPIP + cc], f1 = fsm[(rp + 1) * EPIP + cc];
            uint32_t hp = packbf2(f0, f1);
            uint32_t lp = packbf2(f0 - bflow(hp), f1 - bfhigh(hp));
            int n = n0 + cc;
            size_t o = ((size_t)(n >> 6) * HDIM + (n & 63)) * S_LEN + m0 + rp;
            *reinterpret_cast<uint32_t*>(H + o) = hp;
            *reinterpret_cast<uint32_t*>(L + o) = lp;
        }
    }
}

// ---------------- HMMA ring attention v3 ----------------
// Scores stored packed (sh|sl) u32; softmax writes eh/el bf16 planes in-place;
// PV builds E A-fragments with ldmatrix. QK is 2-term (K single bf16).
#define AQ      32
#define ROWB    4144                    // score row pitch bytes (conflict-free LDSM)
#define EP      1036                    // score row pitch in u32
#define EBYTES  (AQ * ROWB)             // 132608
#define ELOFF   2064                    // el plane byte offset within row
#define KPITCH  144
#define VPITCH  272
#define KTILE   (128 * KPITCH)
#define QPITCH  144
#define OFF_KBUF EBYTES
#define OFF_Q    (OFF_KBUF + 4 * KTILE)
#define OFF_DSH  (OFF_Q + 2 * 32 * QPITCH)
#define ASMEM    (OFF_DSH + 128)

__global__ __launch_bounds__(256) void attn2_k(
    const __nv_bfloat16* __restrict__ Qh, const __nv_bfloat16* __restrict__ Ql,
    const __nv_bfloat16* __restrict__ Kh,
    const __nv_bfloat16* __restrict__ Vh, const __nv_bfloat16* __restrict__ Vl,
    __nv_bfloat16* __restrict__ Oh, __nv_bfloat16* __restrict__ Ol)
{
    extern __shared__ char smraw[];
    float* dsh = reinterpret_cast<float*>(smraw + OFF_DSH);
    const uint32_t sb = smem_u32(smraw);

    const int tid = threadIdx.x, wid = tid >> 5, lane = tid & 31;
    const int g = lane >> 2, tg = lane & 3;
    const int h = blockIdx.y, q0 = blockIdx.x * AQ;

    if (tid < 32) dsh[tid] = 0.f;
    {
        int r = tid >> 3, q = tid & 7;
        const size_t go = ((size_t)h * S_LEN + q0 + r) * HDIM + q * 8;
        CP_ASYNC16(sb + OFF_Q + r * QPITCH + q * 16, Qh + go);
        CP_ASYNC16(sb + OFF_Q + 32 * QPITCH + r * QPITCH + q * 16, Ql + go);
    }
    CP_COMMIT(); CP_WAIT0();
    __syncthreads();

    uint32_t qfh[2][4][4], qfl[2][4][4];
    {
        int rA = lane & 15, cb = (lane >> 4) * 16;
#pragma unroll
        for (int mt = 0; mt < 2; mt++)
#pragma unroll
            for (int kt = 0; kt < 4; kt++) {
                uint32_t a = sb + OFF_Q + (mt * 16 + rA) * QPITCH + kt * 32 + cb;
                LDSM_X4(qfh[mt][kt][0], qfh[mt][kt][1], qfh[mt][kt][2], qfh[mt][kt][3], a);
                LDSM_X4(qfl[mt][kt][0], qfl[mt][kt][1], qfl[mt][kt][2], qfl[mt][kt][3],
                        a + 32 * QPITCH);
            }
    }

    float num[2][4];
#pragma unroll
    for (int n = 0; n < 2; n++)
#pragma unroll
        for (int r = 0; r < 4; r++) num[n][r] = 0.f;

    const int mtv = wid >> 2, np = wid & 3;

    auto stageK = [&](int blk, int c, int b) {
        const uint32_t dst = sb + OFF_KBUF + b * 2 * KTILE;
        const size_t base = ((size_t)h * S_LEN + blk * 1024 + c * 128) * HDIM;
#pragma unroll
        for (int i = 0; i < 4; i++) {
            int e = tid + i * 256;
            int r = e >> 3, q = e & 7;
            CP_ASYNC16(dst + r * KPITCH + q * 16, Kh + base + (size_t)r * HDIM + q * 8);
        }
    };
    auto stageV = [&](int blk, int c, int b) {
        const uint32_t dst = sb + OFF_KBUF + b * 2 * KTILE;
        const size_t base = (size_t)h * HDIM * S_LEN + blk * 1024 + c * 128;
#pragma unroll
        for (int i = 0; i < 4; i++) {
            int e = tid + i * 256;
            int r = e >> 4, q = e & 15;
            CP_ASYNC16(dst + r * VPITCH + q * 16, Vh + base + (size_t)r * S_LEN + q * 8);
            CP_ASYNC16(dst + KTILE + r * VPITCH + q * 16, Vl + base + (size_t)r * S_LEN + q * 8);
        }
    };

    for (int blk = 0; blk < NBLK; blk++) {
        // ================= QK^T (2-term) =================
        stageK(blk, 0, 0); CP_COMMIT();
        for (int c = 0; c < 8; c++) {
            __syncthreads();
            if (c < 7) { stageK(blk, c + 1, (c + 1) & 1); CP_COMMIT(); CP_WAIT1(); }
            else       { CP_WAIT0(); }
            __syncthreads();

            const uint32_t kb = sb + OFF_KBUF + (c & 1) * 2 * KTILE;
            const int rB = wid * 16 + ((lane >> 4) & 1) * 8 + (lane & 7);
            const int cB = ((lane >> 3) & 1) * 16;

            float acc[2][2][4];
#pragma unroll
            for (int mt = 0; mt < 2; mt++)
#pragma unroll
                for (int nt = 0; nt < 2; nt++)
#pragma unroll
                    for (int r = 0; r < 4; r++) acc[mt][nt][r] = 0.f;

#pragma unroll
            for (int kt = 0; kt < 4; kt++) {
                uint32_t bh[4];
                LDSM_X4(bh[0], bh[1], bh[2], bh[3], kb + rB * KPITCH + kt * 32 + cB);
#pragma unroll
                for (int mt = 0; mt < 2; mt++)
#pragma unroll
                    for (int nt = 0; nt < 2; nt++) {
                        MMA16816(acc[mt][nt], qfh[mt][kt], &bh[nt * 2]);
                        MMA16816(acc[mt][nt], qfl[mt][kt], &bh[nt * 2]);
                    }
            }
            uint32_t* ep = reinterpret_cast<uint32_t*>(smraw);
#pragma unroll
            for (int mt = 0; mt < 2; mt++)
#pragma unroll
                for (int nt = 0; nt < 2; nt++) {
                    int row = mt * 16 + g;
                    int col = c * 128 + wid * 16 + nt * 8 + tg * 2;
                    uint2 p0 = make_uint2(packsc(acc[mt][nt][0] * 0.125f),
                                          packsc(acc[mt][nt][1] * 0.125f));
                    uint2 p1 = make_uint2(packsc(acc[mt][nt][2] * 0.125f),
                                          packsc(acc[mt][nt][3] * 0.125f));
                    *reinterpret_cast<uint2*>(ep + row * EP + col) = p0;
                    *reinterpret_cast<uint2*>(ep + (row + 8) * EP + col) = p1;
                }
        }
        __syncthreads();

        stageV(blk, 0, 0); CP_COMMIT();

        // ============ softmax: row in regs, write eh/el planes ============
#pragma unroll
        for (int rr = 0; rr < 4; rr++) {
            const int row = wid * 4 + rr;
            char* rowp = smraw + row * ROWB;
            uint4 pk[8];
            float m = -1e30f;
#pragma unroll
            for (int i = 0; i < 8; i++) {
                pk[i] = reinterpret_cast<uint4*>(rowp)[lane + 32 * i];
                float s0 = bflow(pk[i].x) + bfhigh(pk[i].x);
                float s1 = bflow(pk[i].y) + bfhigh(pk[i].y);
                float s2 = bflow(pk[i].z) + bfhigh(pk[i].z);
                float s3 = bflow(pk[i].w) + bfhigh(pk[i].w);
                m = fmaxf(m, fmaxf(fmaxf(s0, s1), fmaxf(s2, s3)));
            }
#pragma unroll
            for (int off = 16; off >= 1; off >>= 1)
                m = fmaxf(m, __shfl_xor_sync(0xffffffffu, m, off));
            const float mb = m * 1.4426950408889634f;
            float den = 0.f;
#pragma unroll
            for (int i = 0; i < 8; i++) {
                float e0 = fex2(fmaf(bflow(pk[i].x) + bfhigh(pk[i].x), 1.4426950408889634f, -mb));
                float e1 = fex2(fmaf(bflow(pk[i].y) + bfhigh(pk[i].y), 1.4426950408889634f, -mb));
                float e2 = fex2(fmaf(bflow(pk[i].z) + bfhigh(pk[i].z), 1.4426950408889634f, -mb));
                float e3 = fex2(fmaf(bflow(pk[i].w) + bfhigh(pk[i].w), 1.4426950408889634f, -mb));
                den += (e0 + e1) + (e2 + e3);
                uint32_t hx = packbf2(e0, e1), hy = packbf2(e2, e3);
                uint32_t lx = packbf2(e0 - bflow(hx), e1 - bfhigh(hx));
                uint32_t ly = packbf2(e2 - bflow(hy), e3 - bfhigh(hy));
                reinterpret_cast<uint2*>(rowp)[lane + 32 * i] = make_uint2(hx, hy);
                reinterpret_cast<uint2*>(rowp + ELOFF)[lane + 32 * i] = make_uint2(lx, ly);
            }
#pragma unroll
            for (int off = 16; off >= 1; off >>= 1)
                den += __shfl_xor_sync(0xffffffffu, den, off);
            if (lane == 0) dsh[row] += den;
        }

        // ================= PV (3-term, E frags via ldmatrix) =================
        for (int c = 0; c < 8; c++) {
            __syncthreads();
            if (c < 7) { stageV(blk, c + 1, (c + 1) & 1); CP_COMMIT(); CP_WAIT1(); }
            else       { CP_WAIT0(); }
            __syncthreads();

            const uint32_t vb = sb + OFF_KBUF + (c & 1) * 2 * KTILE;
            const int rB = np * 16 + ((lane >> 4) & 1) * 8 + (lane & 7);
            const int cB = ((lane >> 3) & 1) * 16;
            const uint32_t ebase = sb + (mtv * 16 + (lane & 15)) * ROWB
                                 + (lane >> 4) * 16 + c * 256;

#pragma unroll
            for (int u = 0; u < 8; u++) {
                uint32_t aH[4], aL[4];
                LDSM_X4(aH[0], aH[1], aH[2], aH[3], ebase + u * 32);
                LDSM_X4(aL[0], aL[1], aL[2], aL[3], ebase + u * 32 + ELOFF);
                uint32_t bh[4], bl[4];
                uint32_t ad = vb + rB * VPITCH + u * 32 + cB;
                LDSM_X4(bh[0], bh[1], bh[2], bh[3], ad);
                LDSM_X4(bl[0], bl[1], bl[2], bl[3], ad + KTILE);
                MMA16816(num[0], aH, &bh[0]);
                MMA16816(num[0], aH, &bl[0]);
                MMA16816(num[0], aL, &bh[0]);
                MMA16816(num[1], aH, &bh[2]);
                MMA16816(num[1], aH, &bl[2]);
                MMA16816(num[1], aL, &bh[2]);
            }
        }
        __syncthreads();
    }

    {
        const int r0 = mtv * 16 + g;
        const float id0 = 1.0f / dsh[r0];
        const float id1 = 1.0f / dsh[r0 + 8];
#pragma unroll
        for (int nt = 0; nt < 2; nt++) {
            const int col = h * HDIM + np * 16 + nt * 8 + tg * 2;
            float o0 = num[nt][0] * id0, o1 = num[nt][1] * id0;
            float o2 = num[nt][2] * id1, o3 = num[nt][3] * id1;
            uint32_t hp0 = packbf2(o0, o1);
            uint32_t lp0 = packbf2(o0 - bflow(hp0), o1 - bfhigh(hp0));
            uint32_t hp1 = packbf2(o2, o3);
            uint32_t lp1 = packbf2(o2 - bflow(hp1), o3 - bfhigh(hp1));
            size_t a0 = (size_t)(q0 + r0) * HID + col;
            size_t a1 = (size_t)(q0 + r0 + 8) * HID + col;
            *reinterpret_cast<uint32_t*>(Oh + a0) = hp0;
            *reinterpret_cast<uint32_t*>(Ol + a0) = lp0;
            *reinterpret_cast<uint32_t*>(Oh + a1) = hp1;
            *reinterpret_cast<uint32_t*>(Ol + a1) = lp1;
        }
    }
}

// ---------------- launch ----------------
extern "C" void kernel_launch(void* const* d_in, const int* in_sizes, int n_in,
                              void* d_out, int out_size)
{
    const float* x = (const float*)d_in[0];
    float* out = (float*)d_out;

    __nv_bfloat16 *Xh, *Xl, *Qh, *Ql, *Kh, *Kl, *Vh, *Vl, *Ah, *Al, *Wh, *Wl;
    cudaGetSymbolAddress((void**)&Xh, g_Xh); cudaGetSymbolAddress((void**)&Xl, g_Xl);
    cudaGetSymbolAddress((void**)&Qh, g_Qh); cudaGetSymbolAddress((void**)&Ql, g_Ql);
    cudaGetSymbolAddress((void**)&Kh, g_Kh); cudaGetSymbolAddress((void**)&Kl, g_Kl);
    cudaGetSymbolAddress((void**)&Vh, g_Vh); cudaGetSymbolAddress((void**)&Vl, g_Vl);
    cudaGetSymbolAddress((void**)&Ah, g_Ah); cudaGetSymbolAddress((void**)&Al, g_Al);
    cudaGetSymbolAddress((void**)&Wh, g_Wh); cudaGetSymbolAddress((void**)&Wl, g_Wl);

    const int gemm_smem = 2 * BUFB;
    cudaFuncSetAttribute(gemmmma_k, cudaFuncAttributeMaxDynamicSharedMemorySize, gemm_smem);
    cudaFuncSetAttribute(attn2_k, cudaFuncAttributeMaxDynamicSharedMemorySize, ASMEM);

    // launch 1
    convhl_k<<<(S_LEN * HID) / 1024, 256>>>(x, Xh, Xl);
    // launch 2 (all four weights)
    convwt_k<<<dim3(HID / 32, HID / 32, 4), 256>>>((const float*)d_in[1], (const float*)d_in[2],
                                                   (const float*)d_in[3], (const float*)d_in[4],
                                                   Wh, Wl);

    dim3 gg(HID / 128, S_LEN / 128);
    // launches 3-5
    gemmmma_k<<<gg, 256, gemm_smem>>>(Xh, Xl, Wh, Wl, nullptr, Qh, Ql, 1);
    gemmmma_k<<<gg, 256, gemm_smem>>>(Xh, Xl, Wh + (size_t)HID * HID, Wl + (size_t)HID * HID,
                                      nullptr, Kh, Kl, 1);
    gemmmma_k<<<gg, 256, gemm_smem>>>(Xh, Xl, Wh + 2 * (size_t)HID * HID, Wl + 2 * (size_t)HID * HID,
                                      nullptr, Vh, Vl, 2);

    // launch 6
    dim3 ag(S_LEN / AQ, HEADS);
    attn2_k<<<ag, 256, ASMEM>>>(Qh, Ql, Kh, Vh, Vl, Ah, Al);

    // launch 7
    gemmmma_k<<<gg, 256, gemm_smem>>>(Ah, Al, Wh + 3 * (size_t)HID * HID, Wl + 3 * (size_t)HID * HID,
                                      out, nullptr, nullptr, 0);
}